// round 17
// baseline (speedup 1.0000x reference)
#include <cuda_runtime.h>
#include <cstdint>

#define BB 8
#define CC 20
#define NN 2048
#define NMS_T 0.45f
#define PRE_T 0.005f
#define SEG 48          // pair-kernel CTAs per batch (edge segments)
#define SEGCAP 8192     // edges per segment in global
#define ECAP 24576      // resolve shared edge cap (96KB); exact flat tail beyond
#define RT 512          // resolve threads
#define NBINS 128
#define NCHUNK (NN / 32)   // 64 chunks of 32 elements
#define NWARPS (SEG * 8)   // pairs warps per batch = 384

// Class-independent geometric suppression edges, per batch, per segment.
__device__ unsigned g_edges[BB][SEG * SEGCAP];
__device__ int g_cnt[BB][SEG];

// monotone nondecreasing binning of x coords (x in [-0.105, 1.105])
__device__ __forceinline__ int xbin(float v) {
    int b = (int)floorf(__fmul_rn(__fadd_rn(v, 0.25f), 80.0f));
    return min(max(b, 0), NBINS - 1);
}

__device__ __forceinline__ float box_area(float4 v) {
    return __fmul_rn(fmaxf(__fsub_rn(v.z, v.x), 0.0f),
                     fmaxf(__fsub_rn(v.w, v.y), 0.0f));
}

// ---- Kernel A: fused deterministic sort + windowed pair enumeration ----
// Each CTA redundantly computes the IDENTICAL stable counting sort (pure
// sums + lane arithmetic on identical inputs -> bit-identical permutation
// in every CTA), then enumerates its share of the windowed triangle.
// Dynamic shared ~66KB -> 3 CTAs/SM; SEG*BB = 384 CTAs = one wave.
extern __shared__ unsigned char dsmA[];

__global__ __launch_bounds__(256)
void pairs_kernel(const float* __restrict__ bbs) {
    float4* sbox = (float4*)dsmA;                       // 32KB sorted boxes
    float* sar = (float*)(sbox + NN);                   // 8KB  sorted areas
    unsigned short* sidx = (unsigned short*)(sar + NN); // 4KB  original idx
    unsigned short* chunkHist = sidx + NN;              // 16KB [NCHUNK][NBINS]
    int* binStart = (int*)(chunkHist + NCHUNK * NBINS); // 516B
    unsigned char* sbin = (unsigned char*)(binStart + NBINS + 1);  // 2KB
    unsigned char* slb = sbin + NN;                     // 2KB lanes-below
    __shared__ int scnt;
    __shared__ int warpSum[8];

    const int b = blockIdx.y;
    const int seg = blockIdx.x;
    const int tid = threadIdx.x;
    const int wid = tid >> 5;
    const int lane = tid & 31;

    if (tid == 0) scnt = 0;
    for (int i = tid; i < NCHUNK * NBINS / 2; i += 256)
        ((unsigned*)chunkHist)[i] = 0;
    __syncthreads();

    const float4* gb = (const float4*)(bbs + (size_t)b * NN * 4);

    // Pass 1: per-chunk bin counts via match_any; cache bin + lanesBelow
    for (int c = wid; c < NCHUNK; c += 8) {             // warp per chunk
        int idx = c * 32 + lane;
        int bin = xbin(gb[idx].x);
        unsigned same = __match_any_sync(0xffffffffu, bin);
        int lb = __popc(same & ((1u << lane) - 1u));
        sbin[idx] = (unsigned char)bin;
        slb[idx] = (unsigned char)lb;
        if (lb == 0) chunkHist[c * NBINS + bin] = (unsigned short)__popc(same);
    }
    __syncthreads();

    // Pass 2a: per-bin exclusive prefix over chunks (parallel across 128 bins)
    if (tid < NBINS) {
        int running = 0;
        #pragma unroll 8
        for (int c = 0; c < NCHUNK; ++c) {
            int t = chunkHist[c * NBINS + tid];
            chunkHist[c * NBINS + tid] = (unsigned short)running;
            running += t;
        }
        binStart[tid] = running;   // per-bin total, temporarily
    }
    __syncthreads();

    // Pass 2b: exclusive scan of 128 bin totals via shfl warp-scan
    if (tid < NBINS) {
        int v = binStart[tid];
        int inc = v;
        #pragma unroll
        for (int off = 1; off < 32; off <<= 1) {
            int n = __shfl_up_sync(0xffffffffu, inc, off);
            if (lane >= off) inc += n;
        }
        if (lane == 31) warpSum[wid] = inc;
    }
    __syncthreads();
    if (tid < NBINS) {
        int base = 0;
        #pragma unroll
        for (int w2 = 0; w2 < 4; ++w2) if (w2 < wid) base += warpSum[w2];
        int v = binStart[tid];
        int inc = v;
        #pragma unroll
        for (int off = 1; off < 32; off <<= 1) {
            int n = __shfl_up_sync(0xffffffffu, inc, off);
            if (lane >= off) inc += n;
        }
        binStart[tid] = base + inc - v;   // exclusive
    }
    if (tid == 0) binStart[NBINS] = NN;
    __syncthreads();

    // Pass 3: scatter to deterministic sorted positions (local shared)
    for (int idx = tid; idx < NN; idx += 256) {
        int bin = sbin[idx];
        int c = idx >> 5;
        int pos = binStart[bin] + chunkHist[c * NBINS + bin] + slb[idx];
        float4 v = gb[idx];
        sbox[pos] = v;
        sar[pos] = box_area(v);
        sidx[pos] = (unsigned short)idx;
    }
    __syncthreads();

    unsigned* el = &g_edges[b][seg * SEGCAP];

    // warp-per-pivot over sorted positions; identical order in every CTA
    // => the triangle partition covers each qualifying pair exactly once
    const int warpGlobal = seg * 8 + wid;      // 0..NWARPS-1
    for (int i = warpGlobal; i < NN - 1; i += NWARPS) {
        float4 p = sbox[i];                    // broadcast LDS
        float pa = sar[i];
        unsigned oi = sidx[i];
        int jmax = binStart[xbin(p.z) + 1];    // all j with x1_j < x2_i lie below
        for (int j = i + 1 + lane; j < jmax; j += 32) {
            float4 q = sbox[j];
            float iw = __fsub_rn(fminf(p.z, q.z), fmaxf(p.x, q.x));
            if (iw <= 0.0f) continue;
            float ih = __fsub_rn(fminf(p.w, q.w), fmaxf(p.y, q.y));
            if (ih <= 0.0f) continue;
            float inter = __fmul_rn(iw, ih);
            float den = fmaxf(__fsub_rn(__fadd_rn(pa, sar[j]), inter), 1e-12f);
            if (__fdiv_rn(inter, den) > NMS_T) {
                int pos = atomicAdd(&scnt, 1);
                if (pos < SEGCAP)
                    el[pos] = (oi << 11) | (unsigned)sidx[j];
            }
        }
    }
    __syncthreads();
    if (tid == 0) g_cnt[b][seg] = min(scnt, SEGCAP);
}

// ---- Kernel B: per-class Gauss-Seidel fixpoint (R13/14-proven) ----
extern __shared__ unsigned dsm_u[];

__device__ __forceinline__ int find_seg(const int* segOff, int pos) {
    int lo = 0, hi = SEG;
    #pragma unroll
    for (int it = 0; it < 6; ++it) {      // 2^6 >= SEG
        int mid = (lo + hi) >> 1;
        if (segOff[mid] <= pos) lo = mid; else hi = mid;
    }
    return lo;
}

__global__ __launch_bounds__(RT)
void resolve_kernel(const float* __restrict__ conf, float* __restrict__ out) {
    unsigned* cb = dsm_u;                // conf bits [NN]
    unsigned* epk = cb + NN;             // packed (hi<<11)|lo edges [ECAP]
    __shared__ int segOff[SEG + 1];
    __shared__ int tmp[SEG];
    __shared__ unsigned keep0m[64], aliveA[64], aliveB[64], supp[64];
    __shared__ int changed;

    const int bc = blockIdx.x;
    const int b = bc / CC;
    const int tid = threadIdx.x;

    const float* cp = conf + (size_t)bc * NN;
    for (int i = tid; i < NN; i += RT) {
        float v = cp[i];
        cb[i] = __float_as_uint(v);
        unsigned m = __ballot_sync(0xffffffffu, v > PRE_T);
        if ((tid & 31) == 0) { keep0m[i >> 5] = m; aliveA[i >> 5] = m; }
    }
    if (tid < SEG) tmp[tid] = g_cnt[b][tid];
    __syncthreads();
    for (int off = 1; off < SEG; off <<= 1) {
        int v = 0;
        if (tid < SEG) { v = tmp[tid]; if (tid >= off) v += tmp[tid - off]; }
        __syncthreads();
        if (tid < SEG) tmp[tid] = v;
        __syncthreads();
    }
    if (tid < SEG) segOff[tid + 1] = tmp[tid];
    if (tid == 0) segOff[0] = 0;
    __syncthreads();

    const int tot = segOff[SEG];
    const int stot = min(tot, ECAP);
    const bool has_tail = (tot > ECAP);
    const unsigned* eb = g_edges[b];

    // flat gather: address-independent edge loads -> full MLP
    for (int pos = tid; pos < stot; pos += RT) {
        int s = find_seg(segOff, pos);
        unsigned u = eb[s * SEGCAP + (pos - segOff[s])];
        int i = (int)(u >> 11), j = (int)(u & 2047u);
        unsigned bi = cb[i], bj = cb[j];
        int hi, lo;
        // conf desc, tie -> lower original index wins (stable argsort)
        if (bi > bj || (bi == bj && i < j)) { hi = i; lo = j; }
        else                                { hi = j; lo = i; }
        epk[pos] = ((unsigned)hi << 11) | (unsigned)lo;
    }
    __syncthreads();

    unsigned* cur = aliveA;
    unsigned* nxt = aliveB;

    for (int round = 0; round < NN; ++round) {
        __syncthreads();
        if (tid < 64) supp[tid] = 0;
        if (tid == 0) changed = 0;
        __syncthreads();

        // Gauss-Seidel: converged round reproduces Jacobi exactly -> same
        // unique fixpoint (= greedy NMS); within-round reads only accelerate.
        for (int e = tid; e < stot; e += RT) {
            unsigned p = epk[e];
            int hi = (int)(p >> 11), lo = (int)(p & 2047u);
            if ((supp[lo >> 5] >> (lo & 31)) & 1u) continue;
            bool ha = ((cur[hi >> 5] >> (hi & 31)) & 1u) &&
                      !((supp[hi >> 5] >> (hi & 31)) & 1u);
            if (ha)
                atomicOr(&supp[lo >> 5], 1u << (lo & 31));
        }

        if (has_tail) {
            for (int pos = ECAP + tid; pos < tot; pos += RT) {
                int s = find_seg(segOff, pos);
                unsigned u = eb[s * SEGCAP + (pos - segOff[s])];
                int i = (int)(u >> 11), j = (int)(u & 2047u);
                unsigned bi = cb[i], bj = cb[j];
                int hi, lo;
                if (bi > bj || (bi == bj && i < j)) { hi = i; lo = j; }
                else                                { hi = j; lo = i; }
                if ((supp[lo >> 5] >> (lo & 31)) & 1u) continue;
                bool ha = ((cur[hi >> 5] >> (hi & 31)) & 1u) &&
                          !((supp[hi >> 5] >> (hi & 31)) & 1u);
                if (ha)
                    atomicOr(&supp[lo >> 5], 1u << (lo & 31));
            }
        }
        __syncthreads();

        if (tid < 64) {
            unsigned na = keep0m[tid] & ~supp[tid];
            nxt[tid] = na;
            if (na != cur[tid]) changed = 1;   // benign race: all write 1
        }
        __syncthreads();

        int ch = changed;
        unsigned* t = cur; cur = nxt; nxt = t;
        if (!ch) break;
    }

    float* op = out + (size_t)bc * NN;
    for (int i = tid; i < NN; i += RT) {
        bool a = (cur[i >> 5] >> (i & 31)) & 1u;
        op[i] = a ? __uint_as_float(cb[i]) : 0.0f;
    }
}

extern "C" void kernel_launch(void* const* d_in, const int* in_sizes, int n_in,
                              void* d_out, int out_size) {
    const float* bbs;
    const float* conf;
    if (in_sizes[0] == BB * NN * 4) {
        bbs = (const float*)d_in[0];
        conf = (const float*)d_in[1];
    } else {
        bbs = (const float*)d_in[1];
        conf = (const float*)d_in[0];
    }
    float* out = (float*)d_out;

    const int smemA = NN * 16 + NN * 4 + NN * 2 + NCHUNK * NBINS * 2
                    + (NBINS + 1) * 4 + NN + NN;        // ~66.6 KB
    const int smemB = (NN + ECAP) * 4;                  // 104 KB
    cudaFuncSetAttribute(pairs_kernel,
        cudaFuncAttributeMaxDynamicSharedMemorySize, smemA);
    cudaFuncSetAttribute(resolve_kernel,
        cudaFuncAttributeMaxDynamicSharedMemorySize, smemB);

    pairs_kernel<<<dim3(SEG, BB), 256, smemA>>>(bbs);
    resolve_kernel<<<BB * CC, RT, smemB>>>(conf, out);
}